// round 11
// baseline (speedup 1.0000x reference)
#include <cuda_runtime.h>
#include <cuda_bf16.h>
#include <stdint.h>
#include <math.h>

#define NB   64
#define NQ   900
#define NT   128
#define NCLS 91
#define NSEG 4
#define SEGW 225    // 4*225 = 900 == NQ
#define CTS  928    // transposed column stride

typedef unsigned long long u64;
typedef unsigned int       u32;

// Transposed cost copy: g_Ct[b][col][q] (column-contiguous, for rescans)
__device__ float g_Ct[(size_t)NB * NT * CTS];
// Per-(batch, segment, column) minimum key, built by cost_kernel via atomicMin.
__device__ u64 g_segmin[(size_t)NB * NSEG * NT];

__device__ __forceinline__ u32 f2ord(float f) {
    u32 u = __float_as_uint(f);
    return (u & 0x80000000u) ? ~u : (u | 0x80000000u);
}
__device__ __forceinline__ u64 umin64(u64 a, u64 b) { return a < b ? a : b; }
__device__ __forceinline__ u32 redux_min(u32 v) {
    u32 r;
    asm("redux.sync.min.u32 %0, %1, 0xffffffff;" : "=r"(r) : "r"(v));
    return r;
}
// exact warp-wide u64 min (keys unique)
__device__ __forceinline__ u64 wredmin(u64 k) {
    u32 hi = (u32)(k >> 32);
    u32 mh = redux_min(hi);
    u32 lo = (hi == mh) ? (u32)k : 0xFFFFFFFFu;
    u32 ml = redux_min(lo);
    return ((u64)mh << 32) | ml;
}

// ---------------------------------------------------------------------------
// Kernel 0: reset segment minima (deterministic, graph-replay-safe).
// ---------------------------------------------------------------------------
__global__ void __launch_bounds__(256) init_kernel() {
    const size_t n = (size_t)NB * NSEG * NT;
    const size_t idx = (size_t)blockIdx.x * 256 + threadIdx.x;
    if (idx < n) g_segmin[idx] = ~0ull;
}

// ---------------------------------------------------------------------------
// Kernel 1: cost matrix (row-major) + transposed copy + segmin atomics.
// ---------------------------------------------------------------------------
__global__ void __launch_bounds__(256) cost_kernel(
    const float* __restrict__ logits,
    const float* __restrict__ pboxes,
    const int*   __restrict__ labels,
    const float* __restrict__ tboxes,
    float* __restrict__ Cout)
{
    const int b    = blockIdx.y;
    const int tid  = threadIdx.x;
    const int lane = tid & 31;
    const int wid  = tid >> 5;
    const int q0   = blockIdx.x * 16;

    __shared__ float4 s_tb[NT];
    __shared__ float4 s_tx[NT];
    __shared__ float  s_ta[NT];
    __shared__ int    s_lab[NT];
    __shared__ float  s_exp[8][92];
    __shared__ float  s_t[16][132];

    if (tid < NT) {
        const float* tb = tboxes + ((size_t)b * NT + tid) * 4;
        float cx = tb[0], cy = tb[1], w = tb[2], h = tb[3];
        s_tb[tid] = make_float4(cx, cy, w, h);
        float x0 = cx - 0.5f * w, y0 = cy - 0.5f * h;
        float x1 = cx + 0.5f * w, y1 = cy + 0.5f * h;
        s_tx[tid] = make_float4(x0, y0, x1, y1);
        s_ta[tid] = (x1 - x0) * (y1 - y0);
        s_lab[tid] = labels[b * NT + tid];
    }
    __syncthreads();

    #pragma unroll
    for (int rr = 0; rr < 2; rr++) {
        const int qi = rr * 8 + wid;
        const int q  = q0 + qi;
        if (q >= NQ) continue;

        const float* lr = logits + ((size_t)b * NQ + q) * NCLS;
        float l0 = lr[lane];
        float l1 = lr[lane + 32];
        float l2 = (lane + 64 < NCLS) ? lr[lane + 64] : -INFINITY;
        float m = fmaxf(fmaxf(l0, l1), l2);
        #pragma unroll
        for (int o = 16; o; o >>= 1) m = fmaxf(m, __shfl_xor_sync(0xffffffffu, m, o));
        float e0 = expf(l0 - m), e1 = expf(l1 - m);
        float e2 = (lane + 64 < NCLS) ? expf(l2 - m) : 0.0f;
        float ssum = e0 + e1 + e2;
        #pragma unroll
        for (int o = 16; o; o >>= 1) ssum += __shfl_xor_sync(0xffffffffu, ssum, o);
        s_exp[wid][lane] = e0;
        s_exp[wid][lane + 32] = e1;
        if (lane + 64 < NCLS) s_exp[wid][lane + 64] = e2;
        __syncwarp();
        float inv = 1.0f / ssum;

        const float* pbp = pboxes + ((size_t)b * NQ + q) * 4;
        float pcx = pbp[0], pcy = pbp[1], pw = pbp[2], ph = pbp[3];
        float px0 = pcx - 0.5f * pw, py0 = pcy - 0.5f * ph;
        float px1 = pcx + 0.5f * pw, py1 = pcy + 0.5f * ph;
        float pa  = (px1 - px0) * (py1 - py0);

        float cst[4];
        #pragma unroll
        for (int r = 0; r < 4; r++) {
            int t = (lane << 2) | r;
            float4 tb = s_tb[t];
            float4 tx = s_tx[t];
            float pl  = s_exp[wid][s_lab[t]] * inv;
            float l1c = fabsf(pcx - tb.x) + fabsf(pcy - tb.y)
                      + fabsf(pw - tb.z) + fabsf(ph - tb.w);
            float ix0 = fmaxf(px0, tx.x), iy0 = fmaxf(py0, tx.y);
            float ix1 = fminf(px1, tx.z), iy1 = fminf(py1, tx.w);
            float inter = fmaxf(ix1 - ix0, 0.0f) * fmaxf(iy1 - iy0, 0.0f);
            float uni   = pa + s_ta[t] - inter;
            float iou   = inter / uni;
            float cx0 = fminf(px0, tx.x), cy0 = fminf(py0, tx.y);
            float cx1 = fmaxf(px1, tx.z), cy1 = fmaxf(py1, tx.w);
            float ac  = fmaxf(cx1 - cx0, 0.0f) * fmaxf(cy1 - cy0, 0.0f);
            float giou = iou - (ac - uni) / ac;
            cst[r] = -pl + 5.0f * l1c - 2.0f * giou;
        }

        float* crow = Cout + ((size_t)b * NQ + q) * NT;
        *(float4*)(crow + (lane << 2)) = make_float4(cst[0], cst[1], cst[2], cst[3]);
        *(float4*)(&s_t[qi][lane << 2]) = make_float4(cst[0], cst[1], cst[2], cst[3]);
    }
    __syncthreads();

    // transpose + segmin atomics: thread -> (col = tid>>1, half = tid&1)
    {
        const int colg = tid >> 1;
        const int half = tid & 1;
        const int a    = q0 + half * 8;
        float v[8];
        #pragma unroll
        for (int k = 0; k < 8; k++) v[k] = s_t[half * 8 + k][colg];

        float* dst = g_Ct + ((size_t)b * NT + colg) * CTS + a;
        *(float4*)(dst)     = make_float4(v[0], v[1], v[2], v[3]);
        *(float4*)(dst + 4) = make_float4(v[4], v[5], v[6], v[7]);

        // rows a..a+7 span at most 2 segments (SEGW=225 > 16)
        const int s0    = a / SEGW;
        const int split = (s0 + 1) * SEGW;
        u64 m0 = ~0ull, m1 = ~0ull;
        #pragma unroll
        for (int k = 0; k < 8; k++) {
            int q = a + k;
            if (q < NQ) {
                u64 key = ((u64)f2ord(v[k]) << 18) | ((u32)q << 8) | (u32)colg;
                if (q < split) m0 = umin64(m0, key);
                else           m1 = umin64(m1, key);
            }
        }
        u64* segb = g_segmin + (size_t)b * NSEG * NT;
        if (m0 != ~0ull) atomicMin(&segb[s0 * NT + colg], m0);
        if (m1 != ~0ull) atomicMin(&segb[(s0 + 1) * NT + colg], m1);
    }
}

// ---------------------------------------------------------------------------
// Kernel 2: greedy matching.  One block per batch; warps 1-7 only help load;
// warp 0 runs the 128 steps with NO block barriers.
// key = (f2ord(v)<<18) | (q<<8) | c == flattened row-major argmin order.
// Invariant: every segmin entry references a live row.
// ---------------------------------------------------------------------------
__global__ void __launch_bounds__(256) greedy_kernel(float* __restrict__ out)
{
    const int b    = blockIdx.x;
    const int tid  = threadIdx.x;
    const int lane = tid & 31;
    const int wid  = tid >> 5;

    __shared__ u64 segmin[NSEG][NT];
    __shared__ u32 rowdead[32];
    __shared__ int s_src[NT], s_tgt[NT];

    // cooperative load of segmin (4 KB)
    {
        const u64* __restrict__ segb = g_segmin + (size_t)b * NSEG * NT;
        for (int idx = tid; idx < NSEG * NT; idx += 256)
            segmin[idx >> 7][idx & 127] = segb[idx];
    }
    if (tid < 32) rowdead[tid] = 0u;
    __syncthreads();

    if (wid != 0) return;

    // register-resident column keys (col = r*32 + lane)
    u64 ck[4];
    #pragma unroll
    for (int r = 0; r < 4; r++) {
        const int c = r * 32 + lane;
        u64 m = segmin[0][c];
        #pragma unroll
        for (int s = 1; s < NSEG; s++) m = umin64(m, segmin[s][c]);
        ck[r] = m;
    }

    for (int t = 0; t < NT; t++) {
        // ---- argmin over 128 register heads ----
        u64 h = umin64(umin64(ck[0], ck[1]), umin64(ck[2], ck[3]));
        u64 m = wredmin(h);
        const int i = (int)((m >> 8) & 0x3FFu);
        const int j = (int)(m & 0xFFu);

        if (lane == 0) {
            s_src[t] = i;
            s_tgt[t] = j;
            rowdead[i >> 5] |= (1u << (i & 31));
        }
        __syncwarp();
        if (t == NT - 1) break;

        const int si = i / SEGW;
        const int qa = si * SEGW;
        const int qb = (qa + SEGW < NQ) ? qa + SEGW : NQ;

        // ---- kill matched column; detect dirty columns (lane owns 4) ----
        u32 dmask = 0;
        #pragma unroll
        for (int r = 0; r < 4; r++) {
            if (ck[r] == m)     { ck[r] = ~0ull; continue; }
            if (ck[r] == ~0ull) continue;
            const int c = r * 32 + lane;
            u64 sm = segmin[si][c];
            if (sm != ~0ull && (int)((sm >> 8) & 0x3FFu) == i) dmask |= (1u << r);
        }

        // ---- serialized warp-cooperative repairs (expected ~0.57/step) ----
        for (;;) {
            u32 act = __ballot_sync(0xffffffffu, dmask != 0);
            if (!act) break;
            const int leader = __ffs(act) - 1;
            const int lr = __shfl_sync(0xffffffffu, (int)(__ffs(dmask) - 1), leader);
            const int c  = lr * 32 + leader;

            const float* col = g_Ct + ((size_t)b * NT + c) * CTS;
            u64 best = ~0ull;
            #pragma unroll
            for (int k = 0; k < 8; k++) {
                const int q = qa + lane + k * 32;
                if (q < qb && !((rowdead[q >> 5] >> (q & 31)) & 1u)) {
                    u64 key = ((u64)f2ord(col[q]) << 18) | ((u32)q << 8) | (u32)c;
                    best = umin64(best, key);
                }
            }
            best = wredmin(best);
            if (lane == leader) {
                segmin[si][c] = best;
                u64 nc = segmin[0][c];
                #pragma unroll
                for (int s = 1; s < NSEG; s++) nc = umin64(nc, segmin[s][c]);
                ck[lr] = nc;
                dmask &= ~(1u << lr);
            }
        }
        __syncwarp();
    }

    __syncwarp();
    #pragma unroll
    for (int r = 0; r < 4; r++) {
        int t = r * 32 + lane;
        out[b * NT + t]           = (float)s_src[t];
        out[NB * NT + b * NT + t] = (float)s_tgt[t];
    }
}

// ---------------------------------------------------------------------------
extern "C" void kernel_launch(void* const* d_in, const int* in_sizes, int n_in,
                              void* d_out, int out_size) {
    const float* logits = (const float*)d_in[0];
    const float* pboxes = (const float*)d_in[1];
    const int*   labels = (const int*)d_in[2];
    const float* tboxes = (const float*)d_in[3];
    float* out = (float*)d_out;

    float* Cout = out + 2 * NB * NT;

    init_kernel<<<(NB * NSEG * NT + 255) / 256, 256>>>();
    dim3 grid1((NQ + 15) / 16, NB);
    cost_kernel<<<grid1, 256>>>(logits, pboxes, labels, tboxes, Cout);
    greedy_kernel<<<NB, 256>>>(out);
}

// round 12
// speedup vs baseline: 1.8233x; 1.8233x over previous
#include <cuda_runtime.h>
#include <cuda_bf16.h>
#include <stdint.h>
#include <math.h>

#define NB   64
#define NQ   900
#define NT   128
#define NCLS 91
#define NSEG 4
#define SEGW 225    // 4*225 = 900 == NQ
#define CTS  928    // transposed column stride

typedef unsigned long long u64;
typedef unsigned int       u32;

// Transposed cost copy: g_Ct[b][col][q] (column-contiguous, for repairs)
__device__ float g_Ct[(size_t)NB * NT * CTS];
// Per-(batch, segment, column) minimum key, built by cost_kernel via atomicMin.
__device__ u64 g_segmin[(size_t)NB * NSEG * NT];

__device__ __forceinline__ u32 f2ord(float f) {
    u32 u = __float_as_uint(f);
    return (u & 0x80000000u) ? ~u : (u | 0x80000000u);
}
__device__ __forceinline__ u64 umin64(u64 a, u64 b) { return a < b ? a : b; }
__device__ __forceinline__ u64 umax64(u64 a, u64 b) { return a < b ? b : a; }
__device__ __forceinline__ u32 redux_min(u32 v) {
    u32 r;
    asm("redux.sync.min.u32 %0, %1, 0xffffffff;" : "=r"(r) : "r"(v));
    return r;
}
// exact warp-wide u64 min (keys unique)
__device__ __forceinline__ u64 wredmin(u64 k) {
    u32 hi = (u32)(k >> 32);
    u32 mh = redux_min(hi);
    u32 lo = (hi == mh) ? (u32)k : 0xFFFFFFFFu;
    u32 ml = redux_min(lo);
    return ((u64)mh << 32) | ml;
}

// ---------------------------------------------------------------------------
// Kernel 0: reset segment minima (deterministic, graph-replay-safe).
// ---------------------------------------------------------------------------
__global__ void __launch_bounds__(256) init_kernel() {
    const size_t n = (size_t)NB * NSEG * NT;
    const size_t idx = (size_t)blockIdx.x * 256 + threadIdx.x;
    if (idx < n) g_segmin[idx] = ~0ull;
}

// ---------------------------------------------------------------------------
// Kernel 1: cost matrix (row-major) + transposed copy + segmin atomics.
// ---------------------------------------------------------------------------
__global__ void __launch_bounds__(256) cost_kernel(
    const float* __restrict__ logits,
    const float* __restrict__ pboxes,
    const int*   __restrict__ labels,
    const float* __restrict__ tboxes,
    float* __restrict__ Cout)
{
    const int b    = blockIdx.y;
    const int tid  = threadIdx.x;
    const int lane = tid & 31;
    const int wid  = tid >> 5;
    const int q0   = blockIdx.x * 16;

    __shared__ float4 s_tb[NT];
    __shared__ float4 s_tx[NT];
    __shared__ float  s_ta[NT];
    __shared__ int    s_lab[NT];
    __shared__ float  s_exp[8][92];
    __shared__ float  s_t[16][132];

    if (tid < NT) {
        const float* tb = tboxes + ((size_t)b * NT + tid) * 4;
        float cx = tb[0], cy = tb[1], w = tb[2], h = tb[3];
        s_tb[tid] = make_float4(cx, cy, w, h);
        float x0 = cx - 0.5f * w, y0 = cy - 0.5f * h;
        float x1 = cx + 0.5f * w, y1 = cy + 0.5f * h;
        s_tx[tid] = make_float4(x0, y0, x1, y1);
        s_ta[tid] = (x1 - x0) * (y1 - y0);
        s_lab[tid] = labels[b * NT + tid];
    }
    __syncthreads();

    #pragma unroll
    for (int rr = 0; rr < 2; rr++) {
        const int qi = rr * 8 + wid;
        const int q  = q0 + qi;
        if (q >= NQ) continue;

        const float* lr = logits + ((size_t)b * NQ + q) * NCLS;
        float l0 = lr[lane];
        float l1 = lr[lane + 32];
        float l2 = (lane + 64 < NCLS) ? lr[lane + 64] : -INFINITY;
        float m = fmaxf(fmaxf(l0, l1), l2);
        #pragma unroll
        for (int o = 16; o; o >>= 1) m = fmaxf(m, __shfl_xor_sync(0xffffffffu, m, o));
        float e0 = expf(l0 - m), e1 = expf(l1 - m);
        float e2 = (lane + 64 < NCLS) ? expf(l2 - m) : 0.0f;
        float ssum = e0 + e1 + e2;
        #pragma unroll
        for (int o = 16; o; o >>= 1) ssum += __shfl_xor_sync(0xffffffffu, ssum, o);
        s_exp[wid][lane] = e0;
        s_exp[wid][lane + 32] = e1;
        if (lane + 64 < NCLS) s_exp[wid][lane + 64] = e2;
        __syncwarp();
        float inv = 1.0f / ssum;

        const float* pbp = pboxes + ((size_t)b * NQ + q) * 4;
        float pcx = pbp[0], pcy = pbp[1], pw = pbp[2], ph = pbp[3];
        float px0 = pcx - 0.5f * pw, py0 = pcy - 0.5f * ph;
        float px1 = pcx + 0.5f * pw, py1 = pcy + 0.5f * ph;
        float pa  = (px1 - px0) * (py1 - py0);

        float cst[4];
        #pragma unroll
        for (int r = 0; r < 4; r++) {
            int t = (lane << 2) | r;
            float4 tb = s_tb[t];
            float4 tx = s_tx[t];
            float pl  = s_exp[wid][s_lab[t]] * inv;
            float l1c = fabsf(pcx - tb.x) + fabsf(pcy - tb.y)
                      + fabsf(pw - tb.z) + fabsf(ph - tb.w);
            float ix0 = fmaxf(px0, tx.x), iy0 = fmaxf(py0, tx.y);
            float ix1 = fminf(px1, tx.z), iy1 = fminf(py1, tx.w);
            float inter = fmaxf(ix1 - ix0, 0.0f) * fmaxf(iy1 - iy0, 0.0f);
            float uni   = pa + s_ta[t] - inter;
            float iou   = inter / uni;
            float cx0 = fminf(px0, tx.x), cy0 = fminf(py0, tx.y);
            float cx1 = fmaxf(px1, tx.z), cy1 = fmaxf(py1, tx.w);
            float ac  = fmaxf(cx1 - cx0, 0.0f) * fmaxf(cy1 - cy0, 0.0f);
            float giou = iou - (ac - uni) / ac;
            cst[r] = -pl + 5.0f * l1c - 2.0f * giou;
        }

        float* crow = Cout + ((size_t)b * NQ + q) * NT;
        *(float4*)(crow + (lane << 2)) = make_float4(cst[0], cst[1], cst[2], cst[3]);
        *(float4*)(&s_t[qi][lane << 2]) = make_float4(cst[0], cst[1], cst[2], cst[3]);
    }
    __syncthreads();

    // transpose + segmin atomics: thread -> (col = tid>>1, half = tid&1)
    {
        const int colg = tid >> 1;
        const int half = tid & 1;
        const int a    = q0 + half * 8;
        float v[8];
        #pragma unroll
        for (int k = 0; k < 8; k++) v[k] = s_t[half * 8 + k][colg];

        float* dst = g_Ct + ((size_t)b * NT + colg) * CTS + a;
        *(float4*)(dst)     = make_float4(v[0], v[1], v[2], v[3]);
        *(float4*)(dst + 4) = make_float4(v[4], v[5], v[6], v[7]);

        const int s0    = a / SEGW;
        const int split = (s0 + 1) * SEGW;
        u64 m0 = ~0ull, m1 = ~0ull;
        #pragma unroll
        for (int k = 0; k < 8; k++) {
            int q = a + k;
            if (q < NQ) {
                u64 key = ((u64)f2ord(v[k]) << 18) | ((u32)q << 8) | (u32)colg;
                if (q < split) m0 = umin64(m0, key);
                else           m1 = umin64(m1, key);
            }
        }
        u64* segb = g_segmin + (size_t)b * NSEG * NT;
        if (m0 != ~0ull) atomicMin(&segb[s0 * NT + colg], m0);
        if (m1 != ~0ull) atomicMin(&segb[(s0 + 1) * NT + colg], m1);
    }
}

// ---------------------------------------------------------------------------
// Kernel 2: greedy via multi-match rounds.  One block (256 thr) per batch.
// Round: sort live column heads asc (warp 0), accept prefix up to first
// row-duplicate (exact greedy steps), then block-parallel column repairs.
// key = (f2ord(v)<<18) | (q<<8) | c == flattened row-major argmin order.
// ---------------------------------------------------------------------------
__global__ void __launch_bounds__(256) greedy_kernel(float* __restrict__ out)
{
    const int b    = blockIdx.x;
    const int tid  = threadIdx.x;
    const int lane = tid & 31;
    const int wid  = tid >> 5;

    __shared__ u64 colkey[NT];        // live column heads; ~0 = matched
    __shared__ u32 rowslot[1024];     // min sorted-rank per row (this round)
    __shared__ u32 rowdead[32];
    __shared__ int dlist[NT];
    __shared__ int s_cnt, s_tbase;
    __shared__ int s_src[NT], s_tgt[NT];

    for (int idx = tid; idx < 1024; idx += 256) rowslot[idx] = 0xFFFFFFFFu;
    if (tid < 32) rowdead[tid] = 0u;
    if (tid == 0) { s_tbase = 0; s_cnt = 0; }
    if (tid < NT) {
        const u64* __restrict__ segb = g_segmin + (size_t)b * NSEG * NT;
        u64 m = segb[tid];
        #pragma unroll
        for (int s = 1; s < NSEG; s++) m = umin64(m, segb[s * NT + tid]);
        colkey[tid] = m;
    }
    __syncthreads();

    for (;;) {
        const int tbase = s_tbase;

        // ---- warp 0: sort heads, accept prefix ----
        if (wid == 0) {
            u64 key[4];
            #pragma unroll
            for (int r = 0; r < 4; r++) key[r] = colkey[(lane << 2) | r];

            // bitonic sort, 128 u64 keys, 4/lane, ascending in idx=(lane<<2)|r
            #pragma unroll
            for (int k = 2; k <= 128; k <<= 1) {
                #pragma unroll
                for (int j = k >> 1; j > 0; j >>= 1) {
                    if (j >= 4) {
                        int lm = j >> 2;
                        #pragma unroll
                        for (int r = 0; r < 4; r++) {
                            u64 o = __shfl_xor_sync(0xffffffffu, key[r], lm);
                            int idx = (lane << 2) | r;
                            bool up  = ((idx & k) == 0);
                            bool low = ((idx & j) == 0);
                            u64 mn = umin64(key[r], o);
                            u64 mx = umax64(key[r], o);
                            key[r] = (up == low) ? mn : mx;
                        }
                    } else if (j == 2) {
                        bool up = (((lane << 2) & k) == 0);
                        { u64 a = key[0], c = key[2];
                          bool sw = up ? (a > c) : (a < c);
                          if (sw) { key[0] = c; key[2] = a; } }
                        { u64 a = key[1], c = key[3];
                          bool sw = up ? (a > c) : (a < c);
                          if (sw) { key[1] = c; key[3] = a; } }
                    } else {
                        { int idx = (lane << 2);
                          bool up = ((idx & k) == 0);
                          u64 a = key[0], c = key[1];
                          bool sw = up ? (a > c) : (a < c);
                          if (sw) { key[0] = c; key[1] = a; } }
                        { int idx = (lane << 2) | 2;
                          bool up = ((idx & k) == 0);
                          u64 a = key[2], c = key[3];
                          bool sw = up ? (a > c) : (a < c);
                          if (sw) { key[2] = c; key[3] = a; } }
                    }
                }
            }

            // duplicate-row detection via rank-min slots
            int rows[4];
            #pragma unroll
            for (int r = 0; r < 4; r++) {
                rows[r] = (int)((key[r] >> 8) & 0x3FFu);
                atomicMin(&rowslot[rows[r]], (u32)((lane << 2) | r));
            }
            __syncwarp();

            u32 fcl = 128;
            int nlv = 0;
            #pragma unroll
            for (int r = 0; r < 4; r++) {
                u32 rank = (u32)((lane << 2) | r);
                if (key[r] != ~0ull) nlv++;
                if (rowslot[rows[r]] != rank && rank < fcl) fcl = rank;
            }
            u32 fc    = redux_min(fcl);
            int nlive = __reduce_add_sync(0xffffffffu, nlv);
            int nacc  = ((int)fc < nlive) ? (int)fc : nlive;

            #pragma unroll
            for (int r = 0; r < 4; r++) {
                int rank = (lane << 2) | r;
                if (rank < nacc) {
                    int c = (int)(key[r] & 0xFFu);
                    int q = rows[r];
                    s_src[tbase + rank] = q;
                    s_tgt[tbase + rank] = c;
                    colkey[c] = ~0ull;
                    atomicOr(&rowdead[q >> 5], 1u << (q & 31));
                }
                rowslot[rows[r]] = 0xFFFFFFFFu;   // lazy reset
            }
            if (lane == 0) { s_tbase = tbase + nacc; s_cnt = 0; }
        }
        __syncthreads();
        if (s_tbase >= NT) break;

        // ---- dirty detection: live column whose head row died ----
        if (tid < NT) {
            u64 kk = colkey[tid];
            if (kk != ~0ull) {
                int q = (int)((kk >> 8) & 0x3FFu);
                if ((rowdead[q >> 5] >> (q & 31)) & 1u) {
                    int p = atomicAdd(&s_cnt, 1);
                    dlist[p] = tid;
                }
            }
        }
        __syncthreads();

        // ---- repairs: one warp per dirty column, coalesced transposed scan ----
        const int cnt = s_cnt;
        for (int idx = wid; idx < cnt; idx += 8) {
            const int c = dlist[idx];
            const float* col = g_Ct + ((size_t)b * NT + c) * CTS;
            u64 best = ~0ull;
            #pragma unroll
            for (int k = 0; k < 29; k++) {
                const int q = lane + k * 32;
                if (q < NQ && !((rowdead[q >> 5] >> (q & 31)) & 1u)) {
                    u64 kk = ((u64)f2ord(col[q]) << 18) | ((u32)q << 8) | (u32)c;
                    best = umin64(best, kk);
                }
            }
            best = wredmin(best);
            if (lane == 0) colkey[c] = best;
        }
        __syncthreads();
    }

    if (tid < NT) {
        out[b * NT + tid]           = (float)s_src[tid];
        out[NB * NT + b * NT + tid] = (float)s_tgt[tid];
    }
}

// ---------------------------------------------------------------------------
extern "C" void kernel_launch(void* const* d_in, const int* in_sizes, int n_in,
                              void* d_out, int out_size) {
    const float* logits = (const float*)d_in[0];
    const float* pboxes = (const float*)d_in[1];
    const int*   labels = (const int*)d_in[2];
    const float* tboxes = (const float*)d_in[3];
    float* out = (float*)d_out;

    float* Cout = out + 2 * NB * NT;

    init_kernel<<<(NB * NSEG * NT + 255) / 256, 256>>>();
    dim3 grid1((NQ + 15) / 16, NB);
    cost_kernel<<<grid1, 256>>>(logits, pboxes, labels, tboxes, Cout);
    greedy_kernel<<<NB, 256>>>(out);
}

// round 13
// speedup vs baseline: 2.6297x; 1.4423x over previous
#include <cuda_runtime.h>
#include <cuda_bf16.h>
#include <stdint.h>
#include <math.h>

#define NB   64
#define NQ   900
#define NT   128
#define NCLS 91
#define NSEG 4
#define SEGW 225    // 4*225 = 900 == NQ
#define CTS  928    // transposed column stride
#define GT   1024   // greedy kernel threads (32 warps)

typedef unsigned long long u64;
typedef unsigned int       u32;

// Transposed cost copy: g_Ct[b][col][q] (column-contiguous, for repairs)
__device__ float g_Ct[(size_t)NB * NT * CTS];
// Per-(batch, segment, column) minimum key, built by cost_kernel via atomicMin.
__device__ u64 g_segmin[(size_t)NB * NSEG * NT];

__device__ __forceinline__ u32 f2ord(float f) {
    u32 u = __float_as_uint(f);
    return (u & 0x80000000u) ? ~u : (u | 0x80000000u);
}
__device__ __forceinline__ u64 umin64(u64 a, u64 b) { return a < b ? a : b; }
__device__ __forceinline__ u64 umax64(u64 a, u64 b) { return a < b ? b : a; }
__device__ __forceinline__ u32 redux_min(u32 v) {
    u32 r;
    asm("redux.sync.min.u32 %0, %1, 0xffffffff;" : "=r"(r) : "r"(v));
    return r;
}
// exact warp-wide u64 min (keys unique)
__device__ __forceinline__ u64 wredmin(u64 k) {
    u32 hi = (u32)(k >> 32);
    u32 mh = redux_min(hi);
    u32 lo = (hi == mh) ? (u32)k : 0xFFFFFFFFu;
    u32 ml = redux_min(lo);
    return ((u64)mh << 32) | ml;
}

// ---------------------------------------------------------------------------
// Kernel 0: reset segment minima (deterministic, graph-replay-safe).
// ---------------------------------------------------------------------------
__global__ void __launch_bounds__(256) init_kernel() {
    const size_t n = (size_t)NB * NSEG * NT;
    const size_t idx = (size_t)blockIdx.x * 256 + threadIdx.x;
    if (idx < n) g_segmin[idx] = ~0ull;
}

// ---------------------------------------------------------------------------
// Kernel 1: cost matrix (row-major) + transposed copy + segmin atomics.
// ---------------------------------------------------------------------------
__global__ void __launch_bounds__(256) cost_kernel(
    const float* __restrict__ logits,
    const float* __restrict__ pboxes,
    const int*   __restrict__ labels,
    const float* __restrict__ tboxes,
    float* __restrict__ Cout)
{
    const int b    = blockIdx.y;
    const int tid  = threadIdx.x;
    const int lane = tid & 31;
    const int wid  = tid >> 5;
    const int q0   = blockIdx.x * 16;

    __shared__ float4 s_tb[NT];
    __shared__ float4 s_tx[NT];
    __shared__ float  s_ta[NT];
    __shared__ int    s_lab[NT];
    __shared__ float  s_exp[8][92];
    __shared__ float  s_t[16][132];

    if (tid < NT) {
        const float* tb = tboxes + ((size_t)b * NT + tid) * 4;
        float cx = tb[0], cy = tb[1], w = tb[2], h = tb[3];
        s_tb[tid] = make_float4(cx, cy, w, h);
        float x0 = cx - 0.5f * w, y0 = cy - 0.5f * h;
        float x1 = cx + 0.5f * w, y1 = cy + 0.5f * h;
        s_tx[tid] = make_float4(x0, y0, x1, y1);
        s_ta[tid] = (x1 - x0) * (y1 - y0);
        s_lab[tid] = labels[b * NT + tid];
    }
    __syncthreads();

    #pragma unroll
    for (int rr = 0; rr < 2; rr++) {
        const int qi = rr * 8 + wid;
        const int q  = q0 + qi;
        if (q >= NQ) continue;

        const float* lr = logits + ((size_t)b * NQ + q) * NCLS;
        float l0 = lr[lane];
        float l1 = lr[lane + 32];
        float l2 = (lane + 64 < NCLS) ? lr[lane + 64] : -INFINITY;
        float m = fmaxf(fmaxf(l0, l1), l2);
        #pragma unroll
        for (int o = 16; o; o >>= 1) m = fmaxf(m, __shfl_xor_sync(0xffffffffu, m, o));
        float e0 = expf(l0 - m), e1 = expf(l1 - m);
        float e2 = (lane + 64 < NCLS) ? expf(l2 - m) : 0.0f;
        float ssum = e0 + e1 + e2;
        #pragma unroll
        for (int o = 16; o; o >>= 1) ssum += __shfl_xor_sync(0xffffffffu, ssum, o);
        s_exp[wid][lane] = e0;
        s_exp[wid][lane + 32] = e1;
        if (lane + 64 < NCLS) s_exp[wid][lane + 64] = e2;
        __syncwarp();
        float inv = 1.0f / ssum;

        const float* pbp = pboxes + ((size_t)b * NQ + q) * 4;
        float pcx = pbp[0], pcy = pbp[1], pw = pbp[2], ph = pbp[3];
        float px0 = pcx - 0.5f * pw, py0 = pcy - 0.5f * ph;
        float px1 = pcx + 0.5f * pw, py1 = pcy + 0.5f * ph;
        float pa  = (px1 - px0) * (py1 - py0);

        float cst[4];
        #pragma unroll
        for (int r = 0; r < 4; r++) {
            int t = (lane << 2) | r;
            float4 tb = s_tb[t];
            float4 tx = s_tx[t];
            float pl  = s_exp[wid][s_lab[t]] * inv;
            float l1c = fabsf(pcx - tb.x) + fabsf(pcy - tb.y)
                      + fabsf(pw - tb.z) + fabsf(ph - tb.w);
            float ix0 = fmaxf(px0, tx.x), iy0 = fmaxf(py0, tx.y);
            float ix1 = fminf(px1, tx.z), iy1 = fminf(py1, tx.w);
            float inter = fmaxf(ix1 - ix0, 0.0f) * fmaxf(iy1 - iy0, 0.0f);
            float uni   = pa + s_ta[t] - inter;
            float iou   = inter / uni;
            float cx0 = fminf(px0, tx.x), cy0 = fminf(py0, tx.y);
            float cx1 = fmaxf(px1, tx.z), cy1 = fmaxf(py1, tx.w);
            float ac  = fmaxf(cx1 - cx0, 0.0f) * fmaxf(cy1 - cy0, 0.0f);
            float giou = iou - (ac - uni) / ac;
            cst[r] = -pl + 5.0f * l1c - 2.0f * giou;
        }

        float* crow = Cout + ((size_t)b * NQ + q) * NT;
        *(float4*)(crow + (lane << 2)) = make_float4(cst[0], cst[1], cst[2], cst[3]);
        *(float4*)(&s_t[qi][lane << 2]) = make_float4(cst[0], cst[1], cst[2], cst[3]);
    }
    __syncthreads();

    // transpose + segmin atomics: thread -> (col = tid>>1, half = tid&1)
    {
        const int colg = tid >> 1;
        const int half = tid & 1;
        const int a    = q0 + half * 8;
        float v[8];
        #pragma unroll
        for (int k = 0; k < 8; k++) v[k] = s_t[half * 8 + k][colg];

        float* dst = g_Ct + ((size_t)b * NT + colg) * CTS + a;
        *(float4*)(dst)     = make_float4(v[0], v[1], v[2], v[3]);
        *(float4*)(dst + 4) = make_float4(v[4], v[5], v[6], v[7]);

        const int s0    = a / SEGW;
        const int split = (s0 + 1) * SEGW;
        u64 m0 = ~0ull, m1 = ~0ull;
        #pragma unroll
        for (int k = 0; k < 8; k++) {
            int q = a + k;
            if (q < NQ) {
                u64 key = ((u64)f2ord(v[k]) << 18) | ((u32)q << 8) | (u32)colg;
                if (q < split) m0 = umin64(m0, key);
                else           m1 = umin64(m1, key);
            }
        }
        u64* segb = g_segmin + (size_t)b * NSEG * NT;
        if (m0 != ~0ull) atomicMin(&segb[s0 * NT + colg], m0);
        if (m1 != ~0ull) atomicMin(&segb[(s0 + 1) * NT + colg], m1);
    }
}

// ---------------------------------------------------------------------------
// Kernel 2: greedy via multi-match rounds.  One block (1024 thr) per batch.
// Round: warp 0 sorts live column heads asc, accepts prefix up to first
// row-duplicate (exact greedy steps); 32 warps then repair dirty columns.
// key = (f2ord(v)<<18) | (q<<8) | c == flattened row-major argmin order.
// ---------------------------------------------------------------------------
__global__ void __launch_bounds__(GT) greedy_kernel(float* __restrict__ out)
{
    const int b    = blockIdx.x;
    const int tid  = threadIdx.x;
    const int lane = tid & 31;
    const int wid  = tid >> 5;

    __shared__ u64 colkey[NT];        // live column heads; ~0 = matched
    __shared__ u32 rowslot[1024];     // min sorted-rank per row (per round)
    __shared__ u32 rowdead[32];
    __shared__ int dlist[NT];
    __shared__ int s_cnt, s_tbase;
    __shared__ int s_src[NT], s_tgt[NT];

    if (tid < 1024) rowslot[tid] = 0xFFFFFFFFu;
    if (tid < 32) rowdead[tid] = 0u;
    if (tid == 0) { s_tbase = 0; s_cnt = 0; }
    if (tid < NT) {
        const u64* __restrict__ segb = g_segmin + (size_t)b * NSEG * NT;
        u64 m = segb[tid];
        #pragma unroll
        for (int s = 1; s < NSEG; s++) m = umin64(m, segb[s * NT + tid]);
        colkey[tid] = m;
    }
    __syncthreads();

    for (;;) {
        const int tbase = s_tbase;

        // ---- warp 0: sort heads, accept prefix ----
        if (wid == 0) {
            u64 key[4];
            #pragma unroll
            for (int r = 0; r < 4; r++) key[r] = colkey[(lane << 2) | r];

            // bitonic sort, 128 u64 keys, 4/lane, ascending in idx=(lane<<2)|r
            #pragma unroll
            for (int k = 2; k <= 128; k <<= 1) {
                #pragma unroll
                for (int j = k >> 1; j > 0; j >>= 1) {
                    if (j >= 4) {
                        int lm = j >> 2;
                        #pragma unroll
                        for (int r = 0; r < 4; r++) {
                            u64 o = __shfl_xor_sync(0xffffffffu, key[r], lm);
                            int idx = (lane << 2) | r;
                            bool up  = ((idx & k) == 0);
                            bool low = ((idx & j) == 0);
                            u64 mn = umin64(key[r], o);
                            u64 mx = umax64(key[r], o);
                            key[r] = (up == low) ? mn : mx;
                        }
                    } else if (j == 2) {
                        bool up = (((lane << 2) & k) == 0);
                        { u64 a = key[0], c = key[2];
                          bool sw = up ? (a > c) : (a < c);
                          if (sw) { key[0] = c; key[2] = a; } }
                        { u64 a = key[1], c = key[3];
                          bool sw = up ? (a > c) : (a < c);
                          if (sw) { key[1] = c; key[3] = a; } }
                    } else {
                        { int idx = (lane << 2);
                          bool up = ((idx & k) == 0);
                          u64 a = key[0], c = key[1];
                          bool sw = up ? (a > c) : (a < c);
                          if (sw) { key[0] = c; key[1] = a; } }
                        { int idx = (lane << 2) | 2;
                          bool up = ((idx & k) == 0);
                          u64 a = key[2], c = key[3];
                          bool sw = up ? (a > c) : (a < c);
                          if (sw) { key[2] = c; key[3] = a; } }
                    }
                }
            }

            // duplicate-row detection via rank-min slots
            int rows[4];
            #pragma unroll
            for (int r = 0; r < 4; r++) {
                rows[r] = (int)((key[r] >> 8) & 0x3FFu);
                atomicMin(&rowslot[rows[r]], (u32)((lane << 2) | r));
            }
            __syncwarp();

            u32 fcl = 128;
            int nlv = 0;
            #pragma unroll
            for (int r = 0; r < 4; r++) {
                u32 rank = (u32)((lane << 2) | r);
                if (key[r] != ~0ull) nlv++;
                if (rowslot[rows[r]] != rank && rank < fcl) fcl = rank;
            }
            u32 fc    = redux_min(fcl);
            int nlive = __reduce_add_sync(0xffffffffu, nlv);
            int nacc  = ((int)fc < nlive) ? (int)fc : nlive;

            #pragma unroll
            for (int r = 0; r < 4; r++) {
                int rank = (lane << 2) | r;
                if (rank < nacc) {
                    int c = (int)(key[r] & 0xFFu);
                    int q = rows[r];
                    s_src[tbase + rank] = q;
                    s_tgt[tbase + rank] = c;
                    colkey[c] = ~0ull;
                    atomicOr(&rowdead[q >> 5], 1u << (q & 31));
                }
                rowslot[rows[r]] = 0xFFFFFFFFu;   // lazy reset
            }
            if (lane == 0) { s_tbase = tbase + nacc; s_cnt = 0; }
        }
        __syncthreads();
        if (s_tbase >= NT) break;

        // ---- dirty detection: live column whose head row died ----
        if (tid < NT) {
            u64 kk = colkey[tid];
            if (kk != ~0ull) {
                int q = (int)((kk >> 8) & 0x3FFu);
                if ((rowdead[q >> 5] >> (q & 31)) & 1u) {
                    int p = atomicAdd(&s_cnt, 1);
                    dlist[p] = tid;
                }
            }
        }
        __syncthreads();

        // ---- repairs: one warp per dirty column, 32 warps in parallel ----
        const int cnt = s_cnt;
        for (int idx = wid; idx < cnt; idx += 32) {
            const int c = dlist[idx];
            const float* col = g_Ct + ((size_t)b * NT + c) * CTS;

            // unconditional coalesced loads first (full MLP) ...
            float v[29];
            #pragma unroll
            for (int k = 0; k < 29; k++) {
                const int q = lane + k * 32;
                v[k] = (q < NQ) ? col[q] : 0.0f;
            }
            // ... then masked min
            u64 best = ~0ull;
            #pragma unroll
            for (int k = 0; k < 29; k++) {
                const int q = lane + k * 32;
                if (q < NQ && !((rowdead[q >> 5] >> (q & 31)) & 1u)) {
                    u64 kk = ((u64)f2ord(v[k]) << 18) | ((u32)q << 8) | (u32)c;
                    best = umin64(best, kk);
                }
            }
            best = wredmin(best);
            if (lane == 0) colkey[c] = best;
        }
        __syncthreads();
    }

    if (tid < NT) {
        out[b * NT + tid]           = (float)s_src[tid];
        out[NB * NT + b * NT + tid] = (float)s_tgt[tid];
    }
}

// ---------------------------------------------------------------------------
extern "C" void kernel_launch(void* const* d_in, const int* in_sizes, int n_in,
                              void* d_out, int out_size) {
    const float* logits = (const float*)d_in[0];
    const float* pboxes = (const float*)d_in[1];
    const int*   labels = (const int*)d_in[2];
    const float* tboxes = (const float*)d_in[3];
    float* out = (float*)d_out;

    float* Cout = out + 2 * NB * NT;

    init_kernel<<<(NB * NSEG * NT + 255) / 256, 256>>>();
    dim3 grid1((NQ + 15) / 16, NB);
    cost_kernel<<<grid1, 256>>>(logits, pboxes, labels, tboxes, Cout);
    greedy_kernel<<<NB, GT>>>(out);
}

// round 15
// speedup vs baseline: 2.8650x; 1.0895x over previous
#include <cuda_runtime.h>
#include <cuda_bf16.h>
#include <stdint.h>
#include <math.h>

#define NB   64
#define NQ   900
#define NT   128
#define NCLS 91
#define CTS  928    // transposed column stride
#define GT   1024   // greedy kernel threads (32 warps)

typedef unsigned long long u64;
typedef unsigned int       u32;

// Transposed cost copy: g_Ct[b][col][q] (column-contiguous)
__device__ float g_Ct[(size_t)NB * NT * CTS];

__device__ __forceinline__ u32 f2ord(float f) {
    u32 u = __float_as_uint(f);
    return (u & 0x80000000u) ? ~u : (u | 0x80000000u);
}
__device__ __forceinline__ u64 umin64(u64 a, u64 b) { return a < b ? a : b; }
__device__ __forceinline__ u32 redux_min(u32 v) {
    u32 r;
    asm("redux.sync.min.u32 %0, %1, 0xffffffff;" : "=r"(r) : "r"(v));
    return r;
}
// exact warp-wide u64 min (keys unique)
__device__ __forceinline__ u64 wredmin(u64 k) {
    u32 hi = (u32)(k >> 32);
    u32 mh = redux_min(hi);
    u32 lo = (hi == mh) ? (u32)k : 0xFFFFFFFFu;
    u32 ml = redux_min(lo);
    return ((u64)mh << 32) | ml;
}
__device__ __forceinline__ u64 mkkey(float v, int q, int c) {
    return ((u64)f2ord(v) << 18) | ((u32)q << 8) | (u32)c;
}

// ---------------------------------------------------------------------------
// Kernel 1: cost matrix (row-major) + transposed copy to g_Ct.
// ---------------------------------------------------------------------------
__global__ void __launch_bounds__(256) cost_kernel(
    const float* __restrict__ logits,
    const float* __restrict__ pboxes,
    const int*   __restrict__ labels,
    const float* __restrict__ tboxes,
    float* __restrict__ Cout)
{
    const int b    = blockIdx.y;
    const int tid  = threadIdx.x;
    const int lane = tid & 31;
    const int wid  = tid >> 5;
    const int q0   = blockIdx.x * 16;

    __shared__ float4 s_tb[NT];
    __shared__ float4 s_tx[NT];
    __shared__ float  s_ta[NT];
    __shared__ int    s_lab[NT];
    __shared__ float  s_exp[8][92];
    __shared__ float  s_t[16][132];

    if (tid < NT) {
        const float* tb = tboxes + ((size_t)b * NT + tid) * 4;
        float cx = tb[0], cy = tb[1], w = tb[2], h = tb[3];
        s_tb[tid] = make_float4(cx, cy, w, h);
        float x0 = cx - 0.5f * w, y0 = cy - 0.5f * h;
        float x1 = cx + 0.5f * w, y1 = cy + 0.5f * h;
        s_tx[tid] = make_float4(x0, y0, x1, y1);
        s_ta[tid] = (x1 - x0) * (y1 - y0);
        s_lab[tid] = labels[b * NT + tid];
    }
    __syncthreads();

    #pragma unroll
    for (int rr = 0; rr < 2; rr++) {
        const int qi = rr * 8 + wid;
        const int q  = q0 + qi;
        if (q >= NQ) continue;

        const float* lr = logits + ((size_t)b * NQ + q) * NCLS;
        float l0 = lr[lane];
        float l1 = lr[lane + 32];
        float l2 = (lane + 64 < NCLS) ? lr[lane + 64] : -INFINITY;
        float m = fmaxf(fmaxf(l0, l1), l2);
        #pragma unroll
        for (int o = 16; o; o >>= 1) m = fmaxf(m, __shfl_xor_sync(0xffffffffu, m, o));
        float e0 = expf(l0 - m), e1 = expf(l1 - m);
        float e2 = (lane + 64 < NCLS) ? expf(l2 - m) : 0.0f;
        float ssum = e0 + e1 + e2;
        #pragma unroll
        for (int o = 16; o; o >>= 1) ssum += __shfl_xor_sync(0xffffffffu, ssum, o);
        s_exp[wid][lane] = e0;
        s_exp[wid][lane + 32] = e1;
        if (lane + 64 < NCLS) s_exp[wid][lane + 64] = e2;
        __syncwarp();
        float inv = 1.0f / ssum;

        const float* pbp = pboxes + ((size_t)b * NQ + q) * 4;
        float pcx = pbp[0], pcy = pbp[1], pw = pbp[2], ph = pbp[3];
        float px0 = pcx - 0.5f * pw, py0 = pcy - 0.5f * ph;
        float px1 = pcx + 0.5f * pw, py1 = pcy + 0.5f * ph;
        float pa  = (px1 - px0) * (py1 - py0);

        float cst[4];
        #pragma unroll
        for (int r = 0; r < 4; r++) {
            int t = (lane << 2) | r;
            float4 tb = s_tb[t];
            float4 tx = s_tx[t];
            float pl  = s_exp[wid][s_lab[t]] * inv;
            float l1c = fabsf(pcx - tb.x) + fabsf(pcy - tb.y)
                      + fabsf(pw - tb.z) + fabsf(ph - tb.w);
            float ix0 = fmaxf(px0, tx.x), iy0 = fmaxf(py0, tx.y);
            float ix1 = fminf(px1, tx.z), iy1 = fminf(py1, tx.w);
            float inter = fmaxf(ix1 - ix0, 0.0f) * fmaxf(iy1 - iy0, 0.0f);
            float uni   = pa + s_ta[t] - inter;
            float iou   = inter / uni;
            float cx0 = fminf(px0, tx.x), cy0 = fminf(py0, tx.y);
            float cx1 = fmaxf(px1, tx.z), cy1 = fmaxf(py1, tx.w);
            float ac  = fmaxf(cx1 - cx0, 0.0f) * fmaxf(cy1 - cy0, 0.0f);
            float giou = iou - (ac - uni) / ac;
            cst[r] = -pl + 5.0f * l1c - 2.0f * giou;
        }

        float* crow = Cout + ((size_t)b * NQ + q) * NT;
        *(float4*)(crow + (lane << 2)) = make_float4(cst[0], cst[1], cst[2], cst[3]);
        *(float4*)(&s_t[qi][lane << 2]) = make_float4(cst[0], cst[1], cst[2], cst[3]);
    }
    __syncthreads();

    // transposed write: thread -> (col = tid>>1, half = tid&1)
    {
        const int colg = tid >> 1;
        const int half = tid & 1;
        float v[8];
        #pragma unroll
        for (int k = 0; k < 8; k++) v[k] = s_t[half * 8 + k][colg];
        float* dst = g_Ct + ((size_t)b * NT + colg) * CTS + q0 + half * 8;
        *(float4*)(dst)     = make_float4(v[0], v[1], v[2], v[3]);
        *(float4*)(dst + 4) = make_float4(v[4], v[5], v[6], v[7]);
    }
}

// ---------------------------------------------------------------------------
// Kernel 2: greedy via sort-free multi-match rounds.  1024 threads per batch.
// Round: propose heads (atomicMin per row) -> Lmin = min loser key ->
// accept all winners with key < Lmin (== sorted prefix to first duplicate,
// exactly greedy) -> repair columns whose head row died.
// key = (f2ord(v)<<18) | (q<<8) | c == flattened row-major argmin order.
// ---------------------------------------------------------------------------
__global__ void __launch_bounds__(GT) greedy_kernel(float* __restrict__ out)
{
    const int b    = blockIdx.x;
    const int tid  = threadIdx.x;
    const int lane = tid & 31;
    const int wid  = tid >> 5;
    const float* __restrict__ Ctb = g_Ct + (size_t)b * NT * CTS;

    __shared__ u64 colkey[NT];      // live column heads; ~0 = matched
    __shared__ u64 rowbest[NQ];     // per-row winner key (round-local)
    __shared__ u64 acclist[NT];
    __shared__ u64 s_lmin;
    __shared__ u32 rowdead[32];
    __shared__ int dlist[NT];
    __shared__ int s_cnt, s_dcnt, s_total;
    __shared__ int s_src[NT], s_tgt[NT];

    if (tid < NQ) rowbest[tid] = ~0ull;
    if (tid < 32) rowdead[tid] = 0u;
    if (tid == 0) s_total = 0;

    // ---- initial heads: warp w -> columns 4w..4w+3 (coalesced) ----
    #pragma unroll
    for (int x = 0; x < 4; x++) {
        const int c = (wid << 2) + x;
        const float* col = Ctb + (size_t)c * CTS;
        float v[29];
        #pragma unroll
        for (int k = 0; k < 29; k++) {
            const int q = lane + k * 32;
            v[k] = (q < NQ) ? col[q] : 0.0f;
        }
        u64 best = ~0ull;
        #pragma unroll
        for (int k = 0; k < 29; k++) {
            const int q = lane + k * 32;
            if (q < NQ) best = umin64(best, mkkey(v[k], q, c));
        }
        best = wredmin(best);
        if (lane == 0) colkey[c] = best;
    }
    __syncthreads();

    for (;;) {
        // ---- phase 1: propose (row winners via atomicMin) ----
        if (tid < NT) {
            u64 k = colkey[tid];
            if (k != ~0ull) atomicMin(&rowbest[(int)((k >> 8) & 0x3FFu)], k);
        }
        if (tid == GT - 1) { s_lmin = ~0ull; s_cnt = 0; s_dcnt = 0; }
        __syncthreads();

        // ---- phase 2: Lmin = min over loser keys ----
        if (tid < NT) {
            u64 k = colkey[tid];
            if (k != ~0ull && rowbest[(int)((k >> 8) & 0x3FFu)] != k)
                atomicMin(&s_lmin, k);
        }
        __syncthreads();

        // ---- phase 3: accept winners with key < Lmin ----
        const int tbase = s_total;
        u64 myk = ~0ull;
        int myrow = -1;
        bool acc = false;
        if (tid < NT) {
            u64 k = colkey[tid];
            if (k != ~0ull) {
                const int q = (int)((k >> 8) & 0x3FFu);
                myk = k; myrow = q;
                if (rowbest[q] == k && k < s_lmin) {
                    acc = true;
                    int p = atomicAdd(&s_cnt, 1);
                    acclist[p] = k;
                    colkey[tid] = ~0ull;
                    atomicOr(&rowdead[q >> 5], 1u << (q & 31));
                }
            }
        }
        __syncthreads();

        // ---- phase 4: rank/store accepted; reset rowbest; dirty detect ----
        const int cnt = s_cnt;
        if (acc) {
            int rank = 0;
            for (int i = 0; i < cnt; i++) rank += (acclist[i] < myk);
            s_src[tbase + rank] = myrow;
            s_tgt[tbase + rank] = (int)(myk & 0xFFu);
        }
        if (myrow >= 0) rowbest[myrow] = ~0ull;   // all proposers reset their slot
        if (tid == GT - 1) s_total = tbase + cnt;
        if (tid < NT) {
            u64 k = colkey[tid];
            if (k != ~0ull) {
                const int q = (int)((k >> 8) & 0x3FFu);
                if ((rowdead[q >> 5] >> (q & 31)) & 1u) {
                    int p = atomicAdd(&s_dcnt, 1);
                    dlist[p] = tid;
                }
            }
        }
        __syncthreads();
        if (tbase + cnt >= NT) break;

        // ---- phase 5: repairs (one warp per dirty column) ----
        const int dcnt = s_dcnt;
        for (int idx = wid; idx < dcnt; idx += 32) {
            const int c = dlist[idx];
            const float* col = Ctb + (size_t)c * CTS;
            float v[29];
            #pragma unroll
            for (int k = 0; k < 29; k++) {
                const int q = lane + k * 32;
                v[k] = (q < NQ) ? col[q] : 0.0f;
            }
            u64 best = ~0ull;
            #pragma unroll
            for (int k = 0; k < 29; k++) {
                const int q = lane + k * 32;
                if (q < NQ && !((rowdead[q >> 5] >> (q & 31)) & 1u))
                    best = umin64(best, mkkey(v[k], q, c));
            }
            best = wredmin(best);
            if (lane == 0) colkey[c] = best;
        }
        __syncthreads();
    }

    if (tid < NT) {
        out[b * NT + tid]           = (float)s_src[tid];
        out[NB * NT + b * NT + tid] = (float)s_tgt[tid];
    }
}

// ---------------------------------------------------------------------------
extern "C" void kernel_launch(void* const* d_in, const int* in_sizes, int n_in,
                              void* d_out, int out_size) {
    const float* logits = (const float*)d_in[0];
    const float* pboxes = (const float*)d_in[1];
    const int*   labels = (const int*)d_in[2];
    const float* tboxes = (const float*)d_in[3];
    float* out = (float*)d_out;

    float* Cout = out + 2 * NB * NT;

    dim3 grid1((NQ + 15) / 16, NB);
    cost_kernel<<<grid1, 256>>>(logits, pboxes, labels, tboxes, Cout);
    greedy_kernel<<<NB, GT>>>(out);
}